// round 12
// baseline (speedup 1.0000x reference)
#include <cuda_runtime.h>

#define BN 1024   // B*N total nodes
#define NN 512    // nodes per batch

// ---------------- device scratch (no allocations allowed) ----------------
__device__ float g_X0[BN * 128];      // concat features after node MLP
__device__ float g_U[BN * 64];        // per-node u = x @ (W1a - W1b) + b1
__device__ float g_V[BN * 64];        // per-node v = x @ W1b
__device__ float g_ec[4][BN * 64];    // 0: ec1_out, 1: x2=ec2+ec1, 2: ec2_raw, 3: x3=ec3+ec2_raw
__device__ int   g_nbr[BN * NN];      // compacted neighbor indices (within-batch j)
__device__ int   g_cnt[BN];           // neighbor counts

// ---------------- K0: node MLP + concat -> g_X0 [BN,128] ----------------
__global__ void node_mlp_kernel(const float* __restrict__ coords,
                                const float* __restrict__ nf,
                                const float* __restrict__ cs,
                                const float* __restrict__ Wh1, const float* __restrict__ bh1,
                                const float* __restrict__ Wh2, const float* __restrict__ bh2) {
    int node = blockIdx.x;
    int t = threadIdx.x;  // 0..63
    __shared__ float x1s[64];
    float c0 = coords[node * 3 + 0];
    float c1 = coords[node * 3 + 1];
    float c2 = coords[node * 3 + 2];
    float a = bh1[t];
    a = fmaf(c0, Wh1[t], a);
    a = fmaf(c1, Wh1[64 + t], a);
    a = fmaf(c2, Wh1[128 + t], a);
    x1s[t] = fmaxf(a, 0.f);
    __syncthreads();
    float acc = bh2[t];
#pragma unroll
    for (int f = 0; f < 64; f++) acc = fmaf(x1s[f], Wh2[f * 64 + t], acc);
    g_X0[node * 128 + t] = fmaxf(acc, 0.f);
    g_X0[node * 128 + 64 + t] = (t < 63) ? nf[node * 63 + t] : cs[node];
}

// ---------------- K1: compact adjacency rows into neighbor lists ----------------
__global__ void build_nbrs_kernel(const float* __restrict__ A) {
    int node = blockIdx.x;            // 0..1023 ; A row offset = node*NN
    __shared__ int cnt_s;
    if (threadIdx.x == 0) cnt_s = 0;
    __syncthreads();
    int j = threadIdx.x;              // blockDim = 512
    if (A[(size_t)node * NN + j] > 0.f) {
        int s = atomicAdd(&cnt_s, 1);
        g_nbr[node * NN + s] = j;
    }
    __syncthreads();
    if (threadIdx.x == 0) g_cnt[node] = cnt_s;
}

// ---------------- K2a: per-node U/V for an EdgeConv layer ----------------
// u = x @ (W1[:F] - W1[F:]) + b1 ; v = x @ W1[F:]
// Then h1_ij = relu(u_i + v_j) reproduces relu([x_i, x_j - x_i] @ W1 + b1) exactly.
template <int F>
__global__ void uv_kernel(const float* __restrict__ W1, const float* __restrict__ b1,
                          int in_id) {
    int node = blockIdx.x;
    int t = threadIdx.x;  // 0..63
    const float* Xin = (F == 128) ? g_X0 : g_ec[in_id];
    __shared__ float xs[F];
#pragma unroll
    for (int f = t; f < F; f += 64) xs[f] = Xin[node * F + f];
    __syncthreads();
    float u = b1[t], v = 0.f;
#pragma unroll
    for (int f = 0; f < F; f++) {
        float x  = xs[f];
        float wa = W1[f * 64 + t];
        float wb = W1[(F + f) * 64 + t];
        u = fmaf(x, wa - wb, u);
        v = fmaf(x, wb, v);
    }
    g_U[node * 64 + t] = u;
    g_V[node * 64 + t] = v;
}

// ---------------- K2b: sparse edge aggregation (layer-2 MLP + masked max) ----------
// out[node] = max_{j in nbrs} relu( relu(u_i + v_j) @ W2 + b2 )  (+ optional residual)
__global__ void agg_kernel(const float* __restrict__ W2, const float* __restrict__ b2,
                           int res_id, int out_id, int raw_id) {
    int node = blockIdx.x;
    int t = threadIdx.x;  // 0..63, thread t owns output channel t
    __shared__ float h1s[2][64];
    __shared__ int js[NN];

    // W2 column t lives in registers: inner loop is pure LDS(broadcast)+FFMA
    float w2c[64];
#pragma unroll
    for (int f = 0; f < 64; f++) w2c[f] = W2[f * 64 + t];

    float u  = g_U[node * 64 + t];
    float bb = b2[t];
    int cnt  = g_cnt[node];
    int base = node & ~(NN - 1);  // batch base in node space

    for (int e = t; e < cnt; e += 64) js[e] = g_nbr[node * NN + e];
    __syncthreads();

    float m = -1e30f;
    float vj = (cnt > 0) ? g_V[(base + js[0]) * 64 + t] : 0.f;
    for (int e = 0; e < cnt; e++) {
        int p = e & 1;
        h1s[p][t] = fmaxf(u + vj, 0.f);
        // prefetch next neighbor's v to hide L2 latency behind the dot
        float vnext = (e + 1 < cnt) ? g_V[(base + js[e + 1]) * 64 + t] : 0.f;
        __syncthreads();
        float acc = bb;
        const float4* h4 = reinterpret_cast<const float4*>(h1s[p]);
#pragma unroll
        for (int q = 0; q < 16; q++) {
            float4 h = h4[q];
            acc = fmaf(h.x, w2c[4 * q + 0], acc);
            acc = fmaf(h.y, w2c[4 * q + 1], acc);
            acc = fmaf(h.z, w2c[4 * q + 2], acc);
            acc = fmaf(h.w, w2c[4 * q + 3], acc);
        }
        m = fmaxf(m, fmaxf(acc, 0.f));
        vj = vnext;
    }

    float o = m;
    if (res_id >= 0) o += g_ec[res_id][node * 64 + t];
    g_ec[out_id][node * 64 + t] = o;
    if (raw_id >= 0) g_ec[raw_id][node * 64 + t] = m;
}

// ---------------- K3: head MLP -> output [BN,3] ----------------
__global__ void head_kernel(const float* __restrict__ Wh6, const float* __restrict__ bh6,
                            const float* __restrict__ Wout, const float* __restrict__ bout,
                            float* __restrict__ out) {
    int node = blockIdx.x;
    int t = threadIdx.x;  // 0..127
    __shared__ float xs[64];
    __shared__ float h6s[128];
    if (t < 64) xs[t] = g_ec[3][node * 64 + t];
    __syncthreads();
    float acc = bh6[t];
#pragma unroll
    for (int f = 0; f < 64; f++) acc = fmaf(xs[f], Wh6[f * 128 + t], acc);
    h6s[t] = fmaxf(acc, 0.f);
    __syncthreads();
    if (t < 3) {
        float o = bout[t];
#pragma unroll
        for (int f = 0; f < 128; f++) o = fmaf(h6s[f], Wout[f * 3 + t], o);
        out[node * 3 + t] = fmaxf(o, 0.f);
    }
}

// ---------------- launch ----------------
extern "C" void kernel_launch(void* const* d_in, const int* in_sizes, int n_in,
                              void* d_out, int out_size) {
    const float* coords = (const float*)d_in[0];
    const float* A      = (const float*)d_in[1];
    const float* nf     = (const float*)d_in[2];
    const float* cs     = (const float*)d_in[3];
    const float* Wh1    = (const float*)d_in[4];
    const float* bh1    = (const float*)d_in[5];
    const float* Wh2    = (const float*)d_in[6];
    const float* bh2    = (const float*)d_in[7];
    const float* e1W1   = (const float*)d_in[8];
    const float* e1b1   = (const float*)d_in[9];
    const float* e1W2   = (const float*)d_in[10];
    const float* e1b2   = (const float*)d_in[11];
    const float* e2W1   = (const float*)d_in[12];
    const float* e2b1   = (const float*)d_in[13];
    const float* e2W2   = (const float*)d_in[14];
    const float* e2b2   = (const float*)d_in[15];
    const float* e3W1   = (const float*)d_in[16];
    const float* e3b1   = (const float*)d_in[17];
    const float* e3W2   = (const float*)d_in[18];
    const float* e3b2   = (const float*)d_in[19];
    const float* Wh6    = (const float*)d_in[20];
    const float* bh6    = (const float*)d_in[21];
    const float* Wout   = (const float*)d_in[22];
    const float* bout   = (const float*)d_in[23];
    float* out = (float*)d_out;

    node_mlp_kernel<<<BN, 64>>>(coords, nf, cs, Wh1, bh1, Wh2, bh2);
    build_nbrs_kernel<<<BN, NN>>>(A);

    // ec1: F=128 input, no residual; raw output -> g_ec[0]
    uv_kernel<128><<<BN, 64>>>(e1W1, e1b1, -1);
    agg_kernel<<<BN, 64>>>(e1W2, e1b2, /*res*/ -1, /*out*/ 0, /*raw*/ -1);

    // ec2: input ec1_out (g_ec[0]); out = raw + ec1_out -> g_ec[1]; raw -> g_ec[2]
    uv_kernel<64><<<BN, 64>>>(e2W1, e2b1, 0);
    agg_kernel<<<BN, 64>>>(e2W2, e2b2, /*res*/ 0, /*out*/ 1, /*raw*/ 2);

    // ec3: input x2 (g_ec[1]); out = raw + ec2_raw (g_ec[2]) -> g_ec[3]
    uv_kernel<64><<<BN, 64>>>(e3W1, e3b1, 1);
    agg_kernel<<<BN, 64>>>(e3W2, e3b2, /*res*/ 2, /*out*/ 3, /*raw*/ -1);

    head_kernel<<<BN, 128>>>(Wh6, bh6, Wout, bout, out);
}